// round 12
// baseline (speedup 1.0000x reference)
#include <cuda_runtime.h>
#include <cuda_bf16.h>
#include <math.h>

// Problem constants
#define BB 64
#define SS 128
#define CC 32
#define DD 512
#define VV 20000
#define BS (BB*SS)          // 8192
#define G4D (4*DD)          // 2048

// ---------------- device scratch (allocation-free rule: __device__ globals) ----
__device__ float g_x[BS*DD];           // 16 MB  visit embeddings summed
__device__ float g_tf[BS*DD];          // 16 MB  time features
__device__ float g_ux[(size_t)BS*G4D]; // 64 MB  input projection
__device__ float g_h[2][BB*DD];        // ping-pong hidden
__device__ float g_c[2][BB*DD];        // ping-pong cell
__device__ float g_hs[(size_t)BB*SS*DD]; // 16 MB all hidden states
__device__ unsigned g_flags[128];      // per-CTA step counters
__device__ unsigned g_release[2][32];  // per-group release words (padded)

// ---------------- f32x2 packed helpers (Blackwell) ----------------------------
__device__ __forceinline__ unsigned long long ffma2(unsigned long long a,
                                                    unsigned long long b,
                                                    unsigned long long c) {
    unsigned long long d;
    asm("fma.rn.f32x2 %0, %1, %2, %3;" : "=l"(d) : "l"(a), "l"(b), "l"(c));
    return d;
}
__device__ __forceinline__ unsigned long long pack2(float lo, float hi) {
    unsigned long long r;
    asm("mov.b64 %0, {%1, %2};" : "=l"(r) : "f"(lo), "f"(hi));
    return r;
}
__device__ __forceinline__ float2 unpack2(unsigned long long v) {
    float2 r;
    asm("mov.b64 {%0, %1}, %2;" : "=f"(r.x), "=f"(r.y) : "l"(v));
    return r;
}
union F4U { float4 f; unsigned long long u[2]; };

__device__ __forceinline__ float sigmoidf_(float x) { return 1.0f / (1.0f + expf(-x)); }

__device__ __forceinline__ void cpasync16(unsigned saddr, const float* g) {
    asm volatile("cp.async.cg.shared.global [%0], [%1], 16;" :: "r"(saddr), "l"(g));
}
__device__ __forceinline__ void cpasync_commit() {
    asm volatile("cp.async.commit_group;");
}
template<int N> __device__ __forceinline__ void cpasync_wait() {
    asm volatile("cp.async.wait_group %0;" :: "n"(N));
}

// ---------------- kernel: zero h0/c0 + reset barrier state ---------------------
__global__ void k_zero() {
    int i = blockIdx.x * blockDim.x + threadIdx.x;
    if (i < BB*DD) { g_h[0][i] = 0.0f; g_c[0][i] = 0.0f; }
    if (i < 128) g_flags[i] = 0u;
    if (i < 64) ((unsigned*)g_release)[i] = 0u;
}

// ---------------- kernel: gather + sum embeddings ------------------------------
__global__ __launch_bounds__(128) void k_gather(const float* __restrict__ emb,
                                                const int* __restrict__ seqs) {
    int bs = blockIdx.x;
    __shared__ int sidx[CC];
    if (threadIdx.x < CC) sidx[threadIdx.x] = seqs[bs*CC + threadIdx.x];
    __syncthreads();
    int d4 = threadIdx.x;  // 0..127
    float4 acc = make_float4(0.f, 0.f, 0.f, 0.f);
#pragma unroll 8
    for (int c = 0; c < CC; c++) {
        const float4* row = (const float4*)(emb + (size_t)sidx[c] * DD);
        float4 v = __ldg(row + d4);
        acc.x += v.x; acc.y += v.y; acc.z += v.z; acc.w += v.w;
    }
    ((float4*)(g_x + (size_t)bs * DD))[d4] = acc;
}

// ---------------- kernel: time feature ----------------------------------------
__global__ __launch_bounds__(512) void k_tf(const float* __restrict__ tstep,
                                            const float* __restrict__ selw,
                                            const float* __restrict__ selb,
                                            const float* __restrict__ timew,
                                            const float* __restrict__ timeb) {
    int b  = blockIdx.x >> 1;
    int s0 = (blockIdx.x & 1) * 64;
    int d  = threadIdx.x;
    float tw[64];
    const float4* twp = (const float4*)(timew + (size_t)d * 64);
#pragma unroll
    for (int i = 0; i < 16; i++) {
        float4 v = __ldg(twp + i);
        tw[i*4+0] = v.x; tw[i*4+1] = v.y; tw[i*4+2] = v.z; tw[i*4+3] = v.w;
    }
    float tb = timeb[d];
    __shared__ float feat[64];
    for (int si = 0; si < 64; si++) {
        int s = s0 + si;
        if (d < 64) {
            float t = tstep[b*SS + s] * (1.0f / 180.0f);
            float v = t * selw[d] + selb[d];
            feat[d] = 1.0f - tanhf(v * v);
        }
        __syncthreads();
        float acc = tb;
#pragma unroll
        for (int k = 0; k < 64; k++) acc += feat[k] * tw[k];
        g_tf[((size_t)b*SS + s) * DD + d] = acc;
        __syncthreads();
    }
}

// ---------------- kernel: ux = x @ U^T + Ub  (SGEMM 8192x2048x512, f32x2) ------
#define TM 128
#define TN 128
#define TK 16
__global__ __launch_bounds__(256, 2) void k_gemm_ux(const float* __restrict__ U,
                                                    const float* __restrict__ Ub) {
    __shared__ float As[2][TK][TM + 4];
    __shared__ float Bs[2][TK][TN + 4];
    int m0 = blockIdx.y * TM;
    int n0 = blockIdx.x * TN;
    int t = threadIdx.x;
    int lrow = t >> 2;          // 0..63
    int lcol = (t & 3) * 4;     // 0,4,8,12

    const float* Aptr = g_x + (size_t)(m0 + lrow) * DD + lcol;
    const float* Bptr = U   + (size_t)(n0 + lrow) * DD + lcol;

    float4 ra[2], rb[2];
    ra[0] = *(const float4*)(Aptr);
    ra[1] = *(const float4*)(Aptr + 64*DD);
    rb[0] = *(const float4*)(Bptr);
    rb[1] = *(const float4*)(Bptr + 64*DD);

    int warp = t >> 5;
    int wm   = warp >> 1;
    int wn   = warp & 1;
    int lane = t & 31;
    int lm   = lane >> 3;
    int ln   = lane & 7;
    int ma   = wm*32 + lm*4;
    int nb   = wn*64 + ln*4;

    unsigned long long acc[4][8];
#pragma unroll
    for (int mp = 0; mp < 4; mp++)
#pragma unroll
        for (int nn = 0; nn < 8; nn++) acc[mp][nn] = 0ull;

#pragma unroll
    for (int i = 0; i < 2; i++) {
        int r = lrow + i*64;
        As[0][lcol+0][r] = ra[i].x; As[0][lcol+1][r] = ra[i].y;
        As[0][lcol+2][r] = ra[i].z; As[0][lcol+3][r] = ra[i].w;
        Bs[0][lcol+0][r] = rb[i].x; Bs[0][lcol+1][r] = rb[i].y;
        Bs[0][lcol+2][r] = rb[i].z; Bs[0][lcol+3][r] = rb[i].w;
    }
    __syncthreads();

    const int NT = DD / TK;  // 32
    for (int kt = 0; kt < NT; kt++) {
        if (kt < NT - 1) {
            const float* ap = Aptr + (kt+1)*TK;
            const float* bp = Bptr + (kt+1)*TK;
            ra[0] = *(const float4*)(ap);
            ra[1] = *(const float4*)(ap + 64*DD);
            rb[0] = *(const float4*)(bp);
            rb[1] = *(const float4*)(bp + 64*DD);
        }
        int buf = kt & 1;
#pragma unroll
        for (int k = 0; k < TK; k++) {
            F4U a0, a1, b0, b1;
            a0.f = *(const float4*)&As[buf][k][ma];
            a1.f = *(const float4*)&As[buf][k][ma+16];
            b0.f = *(const float4*)&Bs[buf][k][nb];
            b1.f = *(const float4*)&Bs[buf][k][nb+32];
            unsigned long long ap2[4] = { a0.u[0], a0.u[1], a1.u[0], a1.u[1] };
            float bv[8] = {b0.f.x,b0.f.y,b0.f.z,b0.f.w,b1.f.x,b1.f.y,b1.f.z,b1.f.w};
            unsigned long long bb2[8];
#pragma unroll
            for (int nn = 0; nn < 8; nn++) bb2[nn] = pack2(bv[nn], bv[nn]);
#pragma unroll
            for (int mp = 0; mp < 4; mp++)
#pragma unroll
                for (int nn = 0; nn < 8; nn++)
                    acc[mp][nn] = ffma2(ap2[mp], bb2[nn], acc[mp][nn]);
        }
        if (kt < NT - 1) {
            __syncthreads();
            int nbuf = buf ^ 1;
#pragma unroll
            for (int i = 0; i < 2; i++) {
                int r = lrow + i*64;
                As[nbuf][lcol+0][r] = ra[i].x; As[nbuf][lcol+1][r] = ra[i].y;
                As[nbuf][lcol+2][r] = ra[i].z; As[nbuf][lcol+3][r] = ra[i].w;
                Bs[nbuf][lcol+0][r] = rb[i].x; Bs[nbuf][lcol+1][r] = rb[i].y;
                Bs[nbuf][lcol+2][r] = rb[i].z; Bs[nbuf][lcol+3][r] = rb[i].w;
            }
            __syncthreads();
        }
    }

    float ub[8];
#pragma unroll
    for (int nn = 0; nn < 8; nn++)
        ub[nn] = Ub[n0 + nb + (nn>>2)*32 + (nn&3)];
#pragma unroll
    for (int mp = 0; mp < 4; mp++) {
#pragma unroll
        for (int e = 0; e < 2; e++) {
            int m = m0 + ma + (mp>>1)*16 + (mp&1)*2 + e;
            float* Crow = g_ux + (size_t)m * G4D + n0;
#pragma unroll
            for (int nc = 0; nc < 2; nc++) {
                float4 v;
                float2 p0 = unpack2(acc[mp][nc*4+0]);
                float2 p1 = unpack2(acc[mp][nc*4+1]);
                float2 p2 = unpack2(acc[mp][nc*4+2]);
                float2 p3 = unpack2(acc[mp][nc*4+3]);
                v.x = (e ? p0.y : p0.x) + ub[nc*4+0];
                v.y = (e ? p1.y : p1.x) + ub[nc*4+1];
                v.z = (e ? p2.y : p2.x) + ub[nc*4+2];
                v.w = (e ? p3.y : p3.x) + ub[nc*4+3];
                *(float4*)(Crow + nb + nc*32) = v;
            }
        }
    }
}

// ---------------- persistent recurrent kernel (all 128 steps) -------------------
// 128 CTAs = 64 jg x 2 bg. CTA = 8 j x 32 b -> 40 output rows (5 gates x 8 j).
// 512 threads, 16 warps = 16 k-slices of 32 (4 warps/SMSP for latency hiding;
// R11's 2/SMSP left a 2x gap to the 128 B/cyc smem-return floor). Thread
// (kq,rq,bq) computes rows r=rq+4i (i<10) x batch bq+8ib (ib<4) over its
// warp's k-slice. Partials pre-summed to fp32, stored as float4 (stride 44),
// reduced by the lower 256 threads.
#define NCTA 128
#define JPC 8
#define BPC 32
#define WROWS 40
#define WPAD 516
#define HPAD 524
#define RSTRF 44                   // floats per thread in reduce area (16B-aligned)
#define RNN_SMEM ((WROWS*WPAD + 2*BPC*HPAD) * 4)   // 216704 B

__global__ __launch_bounds__(512) void k_rnn(
        const float* __restrict__ Wall, const float* __restrict__ Wallb,
        const float* __restrict__ Wd,   const float* __restrict__ Wdb) {
    extern __shared__ float sm[];
    float* W  = sm;                       // 40 x 516
    float* HS = W + WROWS*WPAD;           // 32 x 524
    float* CS = HS + BPC*HPAD;            // 32 x 524
    float* redf = HS;                     // reduce area aliases HS/CS head (90KB)

    unsigned HSu = (unsigned)__cvta_generic_to_shared(HS);
    unsigned CSu = (unsigned)__cvta_generic_to_shared(CS);

    int t    = threadIdx.x;
    int lane = t & 31;
    int kq   = t >> 5;          // warp id = k-slice 0..15 (32 k each)
    int rq   = (t >> 3) & 3;    // row group
    int bq   = t & 7;           // batch group
    int jg = blockIdx.x & 63;
    int bg = blockIdx.x >> 6;
    int j0 = jg * JPC;
    int b0 = bg * BPC;

    // ---- weights: warp kq loads its own 32-wide k-slice of all 40 rows ----
#pragma unroll
    for (int i = 0; i < 10; i++) {
        int lin = i*32 + lane;            // 0..319
        int row = lin >> 3, c4 = lin & 7;
        int g = row >> 3, jj2 = row & 7;
        const float* src = (g < 4)
            ? Wall + (size_t)(g*DD + j0 + jj2) * DD + kq*32 + c4*4
            : Wd   + (size_t)(j0 + jj2) * DD + kq*32 + c4*4;
        *(float4*)(W + row*WPAD + kq*32 + c4*4) = *(const float4*)src;
    }
    __syncwarp();

    // epilogue mapping: thread t (<256) -> (b_e, jj_e)
    int b_e  = (t & 255) >> 3;  // 0..31
    int jj_e = t & 7;
    int gb_e = b0 + b_e;
    int j_e  = j0 + jj_e;

    float wdb  = __ldg(Wdb + j_e);
    float wab0 = __ldg(Wallb + 0*DD + j_e);
    float wab1 = __ldg(Wallb + 1*DD + j_e);
    float wab2 = __ldg(Wallb + 2*DD + j_e);
    float wab3 = __ldg(Wallb + 3*DD + j_e);

    // prefetch step-0 tf/ux (lower 256 only)
    float tfv = 0.f, ux0 = 0.f, ux1 = 0.f, ux2 = 0.f, ux3 = 0.f;
    if (t < 256) {
        tfv = __ldg(g_tf + ((size_t)gb_e * SS + 0) * DD + j_e);
        const float* uxr = g_ux + ((size_t)gb_e * SS + 0) * G4D;
        ux0 = __ldg(uxr + 0*DD + j_e);
        ux1 = __ldg(uxr + 1*DD + j_e);
        ux2 = __ldg(uxr + 2*DD + j_e);
        ux3 = __ldg(uxr + 3*DD + j_e);
    }

    for (int s = 0; s < SS; s++) {
        const float* h_in = g_h[s & 1];
        const float* c_in = g_c[s & 1];
        float* h_out = g_h[(s + 1) & 1];
        float* c_out = g_c[(s + 1) & 1];
        size_t bsoff = ((size_t)gb_e * SS + s);

        // ---- per-warp cp.async: own 32-wide k-slice of h/c, 2 halves ----
#pragma unroll
        for (int hh = 0; hh < 2; hh++) {
#pragma unroll
            for (int i = 0; i < 4; i++) {
                int lin = i*32 + lane;    // 0..127
                int row = lin >> 2, c4 = lin & 3;
                int col = kq*32 + hh*16 + c4*4;
                unsigned so = (unsigned)((row*HPAD + col) * 4);
                cpasync16(HSu + so, h_in + (size_t)(b0+row)*DD + col);
                cpasync16(CSu + so, c_in + (size_t)(b0+row)*DD + col);
            }
            cpasync_commit();
        }

        unsigned long long acc[10][4];
#pragma unroll
        for (int i = 0; i < 10; i++)
#pragma unroll
            for (int ib = 0; ib < 4; ib++) acc[i][ib] = 0ull;

        // ---- compute: rows r=rq+4i, batch b=bq+8ib, own k-slice (16 k2) ----
#pragma unroll
        for (int hh = 0; hh < 2; hh++) {
            if (hh == 0) cpasync_wait<1>(); else cpasync_wait<0>();
            __syncwarp();
#pragma unroll 2
            for (int mm = 0; mm < 8; mm++) {
                int off = kq*32 + hh*16 + mm*2;
                unsigned long long hp[4], cp[4], wp[10];
#pragma unroll
                for (int ib = 0; ib < 4; ib++) {
                    hp[ib] = *(const unsigned long long*)(HS + (bq + 8*ib)*HPAD + off);
                    cp[ib] = *(const unsigned long long*)(CS + (bq + 8*ib)*HPAD + off);
                }
#pragma unroll
                for (int i = 0; i < 10; i++)
                    wp[i] = *(const unsigned long long*)(W + (rq + 4*i)*WPAD + off);
#pragma unroll
                for (int i = 0; i < 10; i++) {
#pragma unroll
                    for (int ib = 0; ib < 4; ib++) {
                        unsigned long long srcv = (i < 8) ? hp[ib] : cp[ib];
                        acc[i][ib] = ffma2(srcv, wp[i], acc[i][ib]);
                    }
                }
            }
        }

        __syncthreads();                 // all warps' compute done; CS fully valid
        float cprev = (t < 256) ? CS[b_e*HPAD + j_e] : 0.0f;
        __syncthreads();                 // cprev reads done before redf overwrites

        // ---- store pre-summed fp32 partials (float4, stride 44 floats) ----
#pragma unroll
        for (int i = 0; i < 10; i++) {
            float v[4];
#pragma unroll
            for (int ib = 0; ib < 4; ib++) {
                float2 p = unpack2(acc[i][ib]);
                v[ib] = p.x + p.y;
            }
            *(float4*)(redf + t*RSTRF + i*4) = make_float4(v[0], v[1], v[2], v[3]);
        }
        __syncthreads();

        // ---- gather + pointwise (lower 256 threads own one (b,j) each) ----
        if (t < 256) {
            float gate[5];
            int bqp = b_e & 7, ibp = b_e >> 3;
#pragma unroll
            for (int g = 0; g < 5; g++) {
                int r = g*8 + jj_e;
                int rqp = r & 3, ip = r >> 2;
                float sv = 0.f;
#pragma unroll
                for (int kk = 0; kk < 16; kk++)
                    sv += redf[(kk*32 + rqp*8 + bqp)*RSTRF + ip*4 + ibp];
                gate[g] = sv;
            }

            float cs1 = tanhf(gate[4] + wdb);
            float fg = sigmoidf_(gate[0] + wab0 + ux0);
            float ig = sigmoidf_(gate[1] + wab1 + ux1);
            float og = sigmoidf_(gate[2] + wab2 + ux2);
            float ct = sigmoidf_(gate[3] + wab3 + ux3);

            float cadj = cprev + cs1 * (tfv - 1.0f);
            float cn   = fg * cadj + ig * ct;
            float hn   = og * tanhf(cn);
            c_out[(size_t)gb_e*DD + j_e] = cn;
            h_out[(size_t)gb_e*DD + j_e] = hn;
            g_hs[bsoff * DD + j_e] = hn;
        }

        if (s < SS - 1) {
            // prefetch next step's tf/ux (hidden under barrier)
            if (t < 256) {
                size_t bsoff1 = bsoff + 1;
                tfv = __ldg(g_tf + bsoff1 * DD + j_e);
                const float* uxr1 = g_ux + bsoff1 * G4D;
                ux0 = __ldg(uxr1 + 0*DD + j_e);
                ux1 = __ldg(uxr1 + 1*DD + j_e);
                ux2 = __ldg(uxr1 + 2*DD + j_e);
                ux3 = __ldg(uxr1 + 3*DD + j_e);
            }

            // ---- half-grid barrier for group bg (64 CTAs), no atomics ----
            __syncthreads();
            if (t == 0) {
                __threadfence();
                *(volatile unsigned*)&g_flags[blockIdx.x] = (unsigned)(s + 1);
            }
            if (jg == 0) {
                if (t < 64) {
                    const volatile unsigned* f = (const volatile unsigned*)&g_flags[bg*64 + t];
                    while (*f < (unsigned)(s + 1)) { }
                    __threadfence();
                }
                __syncthreads();
                if (t == 0) {
                    *(volatile unsigned*)&g_release[bg][0] = (unsigned)(s + 1);
                }
            } else {
                if (t == 0) {
                    const volatile unsigned* r = (const volatile unsigned*)&g_release[bg][0];
                    while (*r < (unsigned)(s + 1)) { }
                    __threadfence();
                }
                __syncthreads();
            }
        }
    }
}

// ---------------- kernel: max-pool over S + output head ------------------------
__global__ __launch_bounds__(512) void k_pool(const float* __restrict__ ow,
                                              const float* __restrict__ ob,
                                              float* __restrict__ out) {
    int b = blockIdx.x;
    int d = threadIdx.x;
    const float* p = g_hs + (size_t)b * SS * DD + d;
    float m = -3.0e38f;
#pragma unroll 8
    for (int s = 0; s < SS; s++) m = fmaxf(m, p[(size_t)s * DD]);
    float s0 = m * ow[d];
    float s1 = m * ow[DD + d];
    __shared__ float r0[512], r1[512];
    r0[d] = s0; r1[d] = s1;
    __syncthreads();
    for (int off = 256; off > 0; off >>= 1) {
        if (d < off) { r0[d] += r0[d + off]; r1[d] += r1[d + off]; }
        __syncthreads();
    }
    if (d == 0) {
        out[b*2 + 0] = r0[0] + ob[0];
        out[b*2 + 1] = r1[0] + ob[1];
    }
}

// ---------------- launch --------------------------------------------------------
extern "C" void kernel_launch(void* const* d_in, const int* in_sizes, int n_in,
                              void* d_out, int out_size) {
    const float* emb   = (const float*)d_in[0];
    const float* Wall  = (const float*)d_in[1];
    const float* Wallb = (const float*)d_in[2];
    const float* U     = (const float*)d_in[3];
    const float* Ub    = (const float*)d_in[4];
    const float* Wd    = (const float*)d_in[5];
    const float* Wdb   = (const float*)d_in[6];
    const float* selw  = (const float*)d_in[7];
    const float* selb  = (const float*)d_in[8];
    const float* timew = (const float*)d_in[9];
    const float* timeb = (const float*)d_in[10];
    const float* outw  = (const float*)d_in[11];
    const float* outb  = (const float*)d_in[12];
    const float* tstep = (const float*)d_in[13];
    const int*   seqs  = (const int*)d_in[14];
    float* out = (float*)d_out;

    static int configured = 0;
    if (!configured) {
        cudaFuncSetAttribute(k_rnn, cudaFuncAttributeMaxDynamicSharedMemorySize, RNN_SMEM);
        configured = 1;
    }

    k_zero<<<128, 256>>>();
    k_gather<<<BS, 128>>>(emb, seqs);
    k_tf<<<128, 512>>>(tstep, selw, selb, timew, timeb);
    k_gemm_ux<<<dim3(G4D/TN, BS/TM), 256>>>(U, Ub);
    k_rnn<<<NCTA, 512, RNN_SMEM>>>(Wall, Wallb, Wd, Wdb);
    k_pool<<<BB, 512>>>(outw, outb, out);
}

// round 13
// speedup vs baseline: 1.5472x; 1.5472x over previous
#include <cuda_runtime.h>
#include <cuda_bf16.h>
#include <math.h>

// Problem constants
#define BB 64
#define SS 128
#define CC 32
#define DD 512
#define VV 20000
#define BS (BB*SS)          // 8192
#define G4D (4*DD)          // 2048

// ---------------- device scratch (allocation-free rule: __device__ globals) ----
__device__ float g_x[BS*DD];           // 16 MB  visit embeddings summed
__device__ float g_tf[BS*DD];          // 16 MB  time features
__device__ float g_ux[(size_t)BS*G4D]; // 64 MB  input projection
__device__ float g_h[2][BB*DD];        // ping-pong hidden
__device__ float g_c[2][BB*DD];        // ping-pong cell
__device__ float g_hs[(size_t)BB*SS*DD]; // 16 MB all hidden states
__device__ unsigned g_flags[128];      // per-CTA step counters
__device__ unsigned g_release[2][32];  // per-group release words (padded)

// ---------------- f32x2 packed helpers (Blackwell) ----------------------------
__device__ __forceinline__ unsigned long long ffma2(unsigned long long a,
                                                    unsigned long long b,
                                                    unsigned long long c) {
    unsigned long long d;
    asm("fma.rn.f32x2 %0, %1, %2, %3;" : "=l"(d) : "l"(a), "l"(b), "l"(c));
    return d;
}
__device__ __forceinline__ unsigned long long pack2(float lo, float hi) {
    unsigned long long r;
    asm("mov.b64 %0, {%1, %2};" : "=l"(r) : "f"(lo), "f"(hi));
    return r;
}
__device__ __forceinline__ float2 unpack2(unsigned long long v) {
    float2 r;
    asm("mov.b64 {%0, %1}, %2;" : "=f"(r.x), "=f"(r.y) : "l"(v));
    return r;
}
union F4U { float4 f; unsigned long long u[2]; };

__device__ __forceinline__ float sigmoidf_(float x) { return 1.0f / (1.0f + expf(-x)); }

__device__ __forceinline__ void cpasync16(unsigned saddr, const float* g) {
    asm volatile("cp.async.cg.shared.global [%0], [%1], 16;" :: "r"(saddr), "l"(g));
}
__device__ __forceinline__ void cpasync_commit() {
    asm volatile("cp.async.commit_group;");
}
template<int N> __device__ __forceinline__ void cpasync_wait() {
    asm volatile("cp.async.wait_group %0;" :: "n"(N));
}

// ---------------- kernel: zero h0/c0 + reset barrier state ---------------------
__global__ void k_zero() {
    int i = blockIdx.x * blockDim.x + threadIdx.x;
    if (i < BB*DD) { g_h[0][i] = 0.0f; g_c[0][i] = 0.0f; }
    if (i < 128) g_flags[i] = 0u;
    if (i < 64) ((unsigned*)g_release)[i] = 0u;
}

// ---------------- kernel: gather + sum embeddings ------------------------------
__global__ __launch_bounds__(128) void k_gather(const float* __restrict__ emb,
                                                const int* __restrict__ seqs) {
    int bs = blockIdx.x;
    __shared__ int sidx[CC];
    if (threadIdx.x < CC) sidx[threadIdx.x] = seqs[bs*CC + threadIdx.x];
    __syncthreads();
    int d4 = threadIdx.x;  // 0..127
    float4 acc = make_float4(0.f, 0.f, 0.f, 0.f);
#pragma unroll 8
    for (int c = 0; c < CC; c++) {
        const float4* row = (const float4*)(emb + (size_t)sidx[c] * DD);
        float4 v = __ldg(row + d4);
        acc.x += v.x; acc.y += v.y; acc.z += v.z; acc.w += v.w;
    }
    ((float4*)(g_x + (size_t)bs * DD))[d4] = acc;
}

// ---------------- kernel: time feature ----------------------------------------
__global__ __launch_bounds__(512) void k_tf(const float* __restrict__ tstep,
                                            const float* __restrict__ selw,
                                            const float* __restrict__ selb,
                                            const float* __restrict__ timew,
                                            const float* __restrict__ timeb) {
    int b  = blockIdx.x >> 1;
    int s0 = (blockIdx.x & 1) * 64;
    int d  = threadIdx.x;
    float tw[64];
    const float4* twp = (const float4*)(timew + (size_t)d * 64);
#pragma unroll
    for (int i = 0; i < 16; i++) {
        float4 v = __ldg(twp + i);
        tw[i*4+0] = v.x; tw[i*4+1] = v.y; tw[i*4+2] = v.z; tw[i*4+3] = v.w;
    }
    float tb = timeb[d];
    __shared__ float feat[64];
    for (int si = 0; si < 64; si++) {
        int s = s0 + si;
        if (d < 64) {
            float t = tstep[b*SS + s] * (1.0f / 180.0f);
            float v = t * selw[d] + selb[d];
            feat[d] = 1.0f - tanhf(v * v);
        }
        __syncthreads();
        float acc = tb;
#pragma unroll
        for (int k = 0; k < 64; k++) acc += feat[k] * tw[k];
        g_tf[((size_t)b*SS + s) * DD + d] = acc;
        __syncthreads();
    }
}

// ---------------- kernel: ux = x @ U^T + Ub  (SGEMM 8192x2048x512, f32x2) ------
#define TM 128
#define TN 128
#define TK 16
__global__ __launch_bounds__(256, 2) void k_gemm_ux(const float* __restrict__ U,
                                                    const float* __restrict__ Ub) {
    __shared__ float As[2][TK][TM + 4];
    __shared__ float Bs[2][TK][TN + 4];
    int m0 = blockIdx.y * TM;
    int n0 = blockIdx.x * TN;
    int t = threadIdx.x;
    int lrow = t >> 2;          // 0..63
    int lcol = (t & 3) * 4;     // 0,4,8,12

    const float* Aptr = g_x + (size_t)(m0 + lrow) * DD + lcol;
    const float* Bptr = U   + (size_t)(n0 + lrow) * DD + lcol;

    float4 ra[2], rb[2];
    ra[0] = *(const float4*)(Aptr);
    ra[1] = *(const float4*)(Aptr + 64*DD);
    rb[0] = *(const float4*)(Bptr);
    rb[1] = *(const float4*)(Bptr + 64*DD);

    int warp = t >> 5;
    int wm   = warp >> 1;
    int wn   = warp & 1;
    int lane = t & 31;
    int lm   = lane >> 3;
    int ln   = lane & 7;
    int ma   = wm*32 + lm*4;
    int nb   = wn*64 + ln*4;

    unsigned long long acc[4][8];
#pragma unroll
    for (int mp = 0; mp < 4; mp++)
#pragma unroll
        for (int nn = 0; nn < 8; nn++) acc[mp][nn] = 0ull;

#pragma unroll
    for (int i = 0; i < 2; i++) {
        int r = lrow + i*64;
        As[0][lcol+0][r] = ra[i].x; As[0][lcol+1][r] = ra[i].y;
        As[0][lcol+2][r] = ra[i].z; As[0][lcol+3][r] = ra[i].w;
        Bs[0][lcol+0][r] = rb[i].x; Bs[0][lcol+1][r] = rb[i].y;
        Bs[0][lcol+2][r] = rb[i].z; Bs[0][lcol+3][r] = rb[i].w;
    }
    __syncthreads();

    const int NT = DD / TK;  // 32
    for (int kt = 0; kt < NT; kt++) {
        if (kt < NT - 1) {
            const float* ap = Aptr + (kt+1)*TK;
            const float* bp = Bptr + (kt+1)*TK;
            ra[0] = *(const float4*)(ap);
            ra[1] = *(const float4*)(ap + 64*DD);
            rb[0] = *(const float4*)(bp);
            rb[1] = *(const float4*)(bp + 64*DD);
        }
        int buf = kt & 1;
#pragma unroll
        for (int k = 0; k < TK; k++) {
            F4U a0, a1, b0, b1;
            a0.f = *(const float4*)&As[buf][k][ma];
            a1.f = *(const float4*)&As[buf][k][ma+16];
            b0.f = *(const float4*)&Bs[buf][k][nb];
            b1.f = *(const float4*)&Bs[buf][k][nb+32];
            unsigned long long ap2[4] = { a0.u[0], a0.u[1], a1.u[0], a1.u[1] };
            float bv[8] = {b0.f.x,b0.f.y,b0.f.z,b0.f.w,b1.f.x,b1.f.y,b1.f.z,b1.f.w};
            unsigned long long bb2[8];
#pragma unroll
            for (int nn = 0; nn < 8; nn++) bb2[nn] = pack2(bv[nn], bv[nn]);
#pragma unroll
            for (int mp = 0; mp < 4; mp++)
#pragma unroll
                for (int nn = 0; nn < 8; nn++)
                    acc[mp][nn] = ffma2(ap2[mp], bb2[nn], acc[mp][nn]);
        }
        if (kt < NT - 1) {
            __syncthreads();
            int nbuf = buf ^ 1;
#pragma unroll
            for (int i = 0; i < 2; i++) {
                int r = lrow + i*64;
                As[nbuf][lcol+0][r] = ra[i].x; As[nbuf][lcol+1][r] = ra[i].y;
                As[nbuf][lcol+2][r] = ra[i].z; As[nbuf][lcol+3][r] = ra[i].w;
                Bs[nbuf][lcol+0][r] = rb[i].x; Bs[nbuf][lcol+1][r] = rb[i].y;
                Bs[nbuf][lcol+2][r] = rb[i].z; Bs[nbuf][lcol+3][r] = rb[i].w;
            }
            __syncthreads();
        }
    }

    float ub[8];
#pragma unroll
    for (int nn = 0; nn < 8; nn++)
        ub[nn] = Ub[n0 + nb + (nn>>2)*32 + (nn&3)];
#pragma unroll
    for (int mp = 0; mp < 4; mp++) {
#pragma unroll
        for (int e = 0; e < 2; e++) {
            int m = m0 + ma + (mp>>1)*16 + (mp&1)*2 + e;
            float* Crow = g_ux + (size_t)m * G4D + n0;
#pragma unroll
            for (int nc = 0; nc < 2; nc++) {
                float4 v;
                float2 p0 = unpack2(acc[mp][nc*4+0]);
                float2 p1 = unpack2(acc[mp][nc*4+1]);
                float2 p2 = unpack2(acc[mp][nc*4+2]);
                float2 p3 = unpack2(acc[mp][nc*4+3]);
                v.x = (e ? p0.y : p0.x) + ub[nc*4+0];
                v.y = (e ? p1.y : p1.x) + ub[nc*4+1];
                v.z = (e ? p2.y : p2.x) + ub[nc*4+2];
                v.w = (e ? p3.y : p3.x) + ub[nc*4+3];
                *(float4*)(Crow + nb + nc*32) = v;
            }
        }
    }
}

// ---------------- persistent recurrent kernel (all 128 steps) -------------------
// 128 CTAs = 64 jg x 2 bg. CTA = 8 j x 32 b -> 40 output rows (5 gates x 8 j).
// 512 threads, 16 warps = 16 k-slices of 32 (4 warps/SMSP latency hiding).
// FFMA2 pairs span TWO OUTPUT COLUMNS (j-even, j-odd), not two k's: accumulator
// file drops 80 -> 40 regs/thread, so 512 threads fit the 128-reg cap without
// spills (R12's failure). Weights stored k-major in smem WS[k][40] (identity
// row order: rows 0..31 = Wall gates [f,i,o,ct] x 8j, rows 32..39 = Wd).
// Thread (kq,rq,bq): rows pair p (p*8+rq*2, +1), p<5, batch bq+8ib (ib<4).
// p<4 -> h operand, p=4 -> c operand (lane-uniform). h/c scalar packed into
// both f32x2 halves via MOV (alu pipe, parallel to fma pipe).
#define NCTA 128
#define JPC 8
#define BPC 32
#define WKP 40                     // WS row stride (floats) per k
#define HPAD 524
#define RSU 21                     // reduce stride per thread (ull)
#define RNN_SMEM ((DD*WKP + 2*BPC*HPAD) * 4)   // 216064 B

__global__ __launch_bounds__(512) void k_rnn(
        const float* __restrict__ Wall, const float* __restrict__ Wallb,
        const float* __restrict__ Wd,   const float* __restrict__ Wdb) {
    extern __shared__ float sm[];
    float* WS = sm;                       // 512 k x 40 rows (k-major)
    float* HS = WS + DD*WKP;              // 32 b x 524
    float* CS = HS + BPC*HPAD;            // 32 b x 524
    unsigned long long* red = (unsigned long long*)HS;  // aliases HS/CS (86KB<134KB)

    unsigned HSu = (unsigned)__cvta_generic_to_shared(HS);
    unsigned CSu = (unsigned)__cvta_generic_to_shared(CS);

    int t    = threadIdx.x;
    int lane = t & 31;
    int kq   = t >> 5;          // warp id = k-slice 0..15 (32 k each)
    int rq   = lane >> 3;       // row-pair group 0..3
    int bq   = lane & 7;        // batch group
    int jg = blockIdx.x & 63;
    int bg = blockIdx.x >> 6;
    int j0 = jg * JPC;
    int b0 = bg * BPC;

    // ---- weights: transpose into k-major smem once. thread t = k column. ----
#pragma unroll
    for (int i = 0; i < 40; i++) {
        int g = i >> 3, jj2 = i & 7;
        const float* src = (i < 32)
            ? Wall + (size_t)(g*DD + j0 + jj2) * DD + t
            : Wd   + (size_t)(j0 + (i - 32)) * DD + t;
        WS[t*WKP + i] = *src;
    }
    __syncthreads();

    // epilogue mapping: thread t (<256) -> (b_e, jj_e)
    int b_e  = (t & 255) >> 3;  // 0..31
    int jj_e = t & 7;
    int gb_e = b0 + b_e;
    int j_e  = j0 + jj_e;

    float wdb  = __ldg(Wdb + j_e);
    float wab0 = __ldg(Wallb + 0*DD + j_e);
    float wab1 = __ldg(Wallb + 1*DD + j_e);
    float wab2 = __ldg(Wallb + 2*DD + j_e);
    float wab3 = __ldg(Wallb + 3*DD + j_e);

    // prefetch step-0 tf/ux (lower 256 only)
    float tfv = 0.f, ux0 = 0.f, ux1 = 0.f, ux2 = 0.f, ux3 = 0.f;
    if (t < 256) {
        tfv = __ldg(g_tf + ((size_t)gb_e * SS + 0) * DD + j_e);
        const float* uxr = g_ux + ((size_t)gb_e * SS + 0) * G4D;
        ux0 = __ldg(uxr + 0*DD + j_e);
        ux1 = __ldg(uxr + 1*DD + j_e);
        ux2 = __ldg(uxr + 2*DD + j_e);
        ux3 = __ldg(uxr + 3*DD + j_e);
    }

    for (int s = 0; s < SS; s++) {
        const float* h_in = g_h[s & 1];
        const float* c_in = g_c[s & 1];
        float* h_out = g_h[(s + 1) & 1];
        float* c_out = g_c[(s + 1) & 1];
        size_t bsoff = ((size_t)gb_e * SS + s);

        // ---- per-warp cp.async: own 32-wide k-slice of h/c, 2 halves ----
#pragma unroll
        for (int hh = 0; hh < 2; hh++) {
#pragma unroll
            for (int i = 0; i < 4; i++) {
                int lin = i*32 + lane;    // 0..127
                int row = lin >> 2, c4 = lin & 3;
                int col = kq*32 + hh*16 + c4*4;
                unsigned so = (unsigned)((row*HPAD + col) * 4);
                cpasync16(HSu + so, h_in + (size_t)(b0+row)*DD + col);
                cpasync16(CSu + so, c_in + (size_t)(b0+row)*DD + col);
            }
            cpasync_commit();
        }

        unsigned long long acc[5][4];
#pragma unroll
        for (int p = 0; p < 5; p++)
#pragma unroll
            for (int ib = 0; ib < 4; ib++) acc[p][ib] = 0ull;

        // ---- compute over own 32-wide k-slice ----
#pragma unroll
        for (int hh = 0; hh < 2; hh++) {
            if (hh == 0) cpasync_wait<1>(); else cpasync_wait<0>();
            __syncwarp();
            int kbase = kq*32 + hh*16;
#pragma unroll
            for (int km2 = 0; km2 < 8; km2++) {
                int k0 = kbase + km2*2;
                unsigned long long hd[4], cd[4];
#pragma unroll
                for (int ib = 0; ib < 4; ib++) {
                    hd[ib] = *(const unsigned long long*)(HS + (bq + 8*ib)*HPAD + k0);
                    cd[ib] = *(const unsigned long long*)(CS + (bq + 8*ib)*HPAD + k0);
                }
#pragma unroll
                for (int e2 = 0; e2 < 2; e2++) {
                    int k = k0 + e2;
                    unsigned long long wpp[5];
#pragma unroll
                    for (int p = 0; p < 5; p++)
                        wpp[p] = *(const unsigned long long*)(WS + k*WKP + p*8 + rq*2);
                    unsigned long long ph[4], pc[4];
#pragma unroll
                    for (int ib = 0; ib < 4; ib++) {
                        float2 hu = unpack2(hd[ib]);
                        float2 cu = unpack2(cd[ib]);
                        float hv = e2 ? hu.y : hu.x;
                        float cv = e2 ? cu.y : cu.x;
                        ph[ib] = pack2(hv, hv);
                        pc[ib] = pack2(cv, cv);
                    }
#pragma unroll
                    for (int p = 0; p < 5; p++) {
#pragma unroll
                        for (int ib = 0; ib < 4; ib++) {
                            unsigned long long srcv = (p < 4) ? ph[ib] : pc[ib];
                            acc[p][ib] = ffma2(srcv, wpp[p], acc[p][ib]);
                        }
                    }
                }
            }
        }

        __syncthreads();                 // all warps' compute done; CS fully valid
        float cprev = (t < 256) ? CS[b_e*HPAD + j_e] : 0.0f;
        __syncthreads();                 // cprev reads done before red overwrites

        // ---- store partials: acc[p][ib] = (out_{j even}, out_{j odd}) ----
#pragma unroll
        for (int p = 0; p < 5; p++)
#pragma unroll
            for (int ib = 0; ib < 4; ib++)
                red[t*RSU + p*4 + ib] = acc[p][ib];
        __syncthreads();

        // ---- gather + pointwise (lower 256 threads own one (b,j) each) ----
        if (t < 256) {
            const float* rf = (const float*)red;
            int rq_s = (jj_e >> 1) & 3;
            int e_s  = jj_e & 1;
            int bq_s = b_e & 7, ib_s = b_e >> 3;
            float gate[5];
#pragma unroll
            for (int g = 0; g < 5; g++) {
                float sv = 0.f;
#pragma unroll
                for (int kk = 0; kk < 16; kk++) {
                    int tsrc = kk*32 + rq_s*8 + bq_s;
                    sv += rf[(tsrc*RSU + g*4 + ib_s)*2 + e_s];
                }
                gate[g] = sv;
            }

            float cs1 = tanhf(gate[4] + wdb);
            float fg = sigmoidf_(gate[0] + wab0 + ux0);
            float ig = sigmoidf_(gate[1] + wab1 + ux1);
            float og = sigmoidf_(gate[2] + wab2 + ux2);
            float ct = sigmoidf_(gate[3] + wab3 + ux3);

            float cadj = cprev + cs1 * (tfv - 1.0f);
            float cn   = fg * cadj + ig * ct;
            float hn   = og * tanhf(cn);
            c_out[(size_t)gb_e*DD + j_e] = cn;
            h_out[(size_t)gb_e*DD + j_e] = hn;
            g_hs[bsoff * DD + j_e] = hn;
        }

        if (s < SS - 1) {
            // prefetch next step's tf/ux (hidden under barrier)
            if (t < 256) {
                size_t bsoff1 = bsoff + 1;
                tfv = __ldg(g_tf + bsoff1 * DD + j_e);
                const float* uxr1 = g_ux + bsoff1 * G4D;
                ux0 = __ldg(uxr1 + 0*DD + j_e);
                ux1 = __ldg(uxr1 + 1*DD + j_e);
                ux2 = __ldg(uxr1 + 2*DD + j_e);
                ux3 = __ldg(uxr1 + 3*DD + j_e);
            }

            // ---- half-grid barrier for group bg (64 CTAs), no atomics ----
            __syncthreads();
            if (t == 0) {
                __threadfence();
                *(volatile unsigned*)&g_flags[blockIdx.x] = (unsigned)(s + 1);
            }
            if (jg == 0) {
                if (t < 64) {
                    const volatile unsigned* f = (const volatile unsigned*)&g_flags[bg*64 + t];
                    while (*f < (unsigned)(s + 1)) { }
                    __threadfence();
                }
                __syncthreads();
                if (t == 0) {
                    *(volatile unsigned*)&g_release[bg][0] = (unsigned)(s + 1);
                }
            } else {
                if (t == 0) {
                    const volatile unsigned* r = (const volatile unsigned*)&g_release[bg][0];
                    while (*r < (unsigned)(s + 1)) { }
                    __threadfence();
                }
                __syncthreads();
            }
        }
    }
}

// ---------------- kernel: max-pool over S + output head ------------------------
__global__ __launch_bounds__(512) void k_pool(const float* __restrict__ ow,
                                              const float* __restrict__ ob,
                                              float* __restrict__ out) {
    int b = blockIdx.x;
    int d = threadIdx.x;
    const float* p = g_hs + (size_t)b * SS * DD + d;
    float m = -3.0e38f;
#pragma unroll 8
    for (int s = 0; s < SS; s++) m = fmaxf(m, p[(size_t)s * DD]);
    float s0 = m * ow[d];
    float s1 = m * ow[DD + d];
    __shared__ float r0[512], r1[512];
    r0[d] = s0; r1[d] = s1;
    __syncthreads();
    for (int off = 256; off > 0; off >>= 1) {
        if (d < off) { r0[d] += r0[d + off]; r1[d] += r1[d + off]; }
        __syncthreads();
    }
    if (d == 0) {
        out[b*2 + 0] = r0[0] + ob[0];
        out[b*2 + 1] = r1[0] + ob[1];
    }
}

// ---------------- launch --------------------------------------------------------
extern "C" void kernel_launch(void* const* d_in, const int* in_sizes, int n_in,
                              void* d_out, int out_size) {
    const float* emb   = (const float*)d_in[0];
    const float* Wall  = (const float*)d_in[1];
    const float* Wallb = (const float*)d_in[2];
    const float* U     = (const float*)d_in[3];
    const float* Ub    = (const float*)d_in[4];
    const float* Wd    = (const float*)d_in[5];
    const float* Wdb   = (const float*)d_in[6];
    const float* selw  = (const float*)d_in[7];
    const float* selb  = (const float*)d_in[8];
    const float* timew = (const float*)d_in[9];
    const float* timeb = (const float*)d_in[10];
    const float* outw  = (const float*)d_in[11];
    const float* outb  = (const float*)d_in[12];
    const float* tstep = (const float*)d_in[13];
    const int*   seqs  = (const int*)d_in[14];
    float* out = (float*)d_out;

    static int configured = 0;
    if (!configured) {
        cudaFuncSetAttribute(k_rnn, cudaFuncAttributeMaxDynamicSharedMemorySize, RNN_SMEM);
        configured = 1;
    }

    k_zero<<<128, 256>>>();
    k_gather<<<BS, 128>>>(emb, seqs);
    k_tf<<<128, 512>>>(tstep, selw, selb, timew, timeb);
    k_gemm_ux<<<dim3(G4D/TN, BS/TM), 256>>>(U, Ub);
    k_rnn<<<NCTA, 512, RNN_SMEM>>>(Wall, Wallb, Wd, Wdb);
    k_pool<<<BB, 512>>>(outw, outb, out);
}

// round 14
// speedup vs baseline: 1.6585x; 1.0720x over previous
#include <cuda_runtime.h>
#include <cuda_bf16.h>
#include <math.h>

// Problem constants
#define BB 64
#define SS 128
#define CC 32
#define DD 512
#define VV 20000
#define BS (BB*SS)          // 8192
#define G4D (4*DD)          // 2048

// ---------------- device scratch (allocation-free rule: __device__ globals) ----
__device__ float g_x[BS*DD];           // 16 MB  visit embeddings summed
__device__ float g_tf[BS*DD];          // 16 MB  time features
__device__ float g_ux[(size_t)BS*G4D]; // 64 MB  input projection
__device__ float g_hT[2][DD*BB];       // ping-pong hidden, TRANSPOSED [j][b]
__device__ float g_cT[2][DD*BB];       // ping-pong cell,   TRANSPOSED [j][b]
__device__ float g_hs[(size_t)BB*SS*DD]; // 16 MB all hidden states [b][s][d]
__device__ unsigned g_flags[128];      // per-CTA step counters
__device__ unsigned g_release[2][32];  // per-group release words (padded)

// ---------------- f32x2 packed helpers (Blackwell) ----------------------------
__device__ __forceinline__ unsigned long long ffma2(unsigned long long a,
                                                    unsigned long long b,
                                                    unsigned long long c) {
    unsigned long long d;
    asm("fma.rn.f32x2 %0, %1, %2, %3;" : "=l"(d) : "l"(a), "l"(b), "l"(c));
    return d;
}
__device__ __forceinline__ unsigned long long pack2(float lo, float hi) {
    unsigned long long r;
    asm("mov.b64 %0, {%1, %2};" : "=l"(r) : "f"(lo), "f"(hi));
    return r;
}
__device__ __forceinline__ float2 unpack2(unsigned long long v) {
    float2 r;
    asm("mov.b64 {%0, %1}, %2;" : "=f"(r.x), "=f"(r.y) : "l"(v));
    return r;
}
union F4U { float4 f; unsigned long long u[2]; };

__device__ __forceinline__ float sigmoidf_(float x) { return 1.0f / (1.0f + expf(-x)); }

__device__ __forceinline__ void cpasync16(unsigned saddr, const float* g) {
    asm volatile("cp.async.cg.shared.global [%0], [%1], 16;" :: "r"(saddr), "l"(g));
}
__device__ __forceinline__ void cpasync_commit() {
    asm volatile("cp.async.commit_group;");
}
template<int N> __device__ __forceinline__ void cpasync_wait() {
    asm volatile("cp.async.wait_group %0;" :: "n"(N));
}

// ---------------- kernel: zero h0/c0 + reset barrier state ---------------------
__global__ void k_zero() {
    int i = blockIdx.x * blockDim.x + threadIdx.x;
    if (i < DD*BB) { g_hT[0][i] = 0.0f; g_cT[0][i] = 0.0f; }
    if (i < 128) g_flags[i] = 0u;
    if (i < 64) ((unsigned*)g_release)[i] = 0u;
}

// ---------------- kernel: gather + sum embeddings ------------------------------
__global__ __launch_bounds__(128) void k_gather(const float* __restrict__ emb,
                                                const int* __restrict__ seqs) {
    int bs = blockIdx.x;
    __shared__ int sidx[CC];
    if (threadIdx.x < CC) sidx[threadIdx.x] = seqs[bs*CC + threadIdx.x];
    __syncthreads();
    int d4 = threadIdx.x;  // 0..127
    float4 acc = make_float4(0.f, 0.f, 0.f, 0.f);
#pragma unroll 8
    for (int c = 0; c < CC; c++) {
        const float4* row = (const float4*)(emb + (size_t)sidx[c] * DD);
        float4 v = __ldg(row + d4);
        acc.x += v.x; acc.y += v.y; acc.z += v.z; acc.w += v.w;
    }
    ((float4*)(g_x + (size_t)bs * DD))[d4] = acc;
}

// ---------------- kernel: time feature ----------------------------------------
__global__ __launch_bounds__(512) void k_tf(const float* __restrict__ tstep,
                                            const float* __restrict__ selw,
                                            const float* __restrict__ selb,
                                            const float* __restrict__ timew,
                                            const float* __restrict__ timeb) {
    int b  = blockIdx.x >> 1;
    int s0 = (blockIdx.x & 1) * 64;
    int d  = threadIdx.x;
    float tw[64];
    const float4* twp = (const float4*)(timew + (size_t)d * 64);
#pragma unroll
    for (int i = 0; i < 16; i++) {
        float4 v = __ldg(twp + i);
        tw[i*4+0] = v.x; tw[i*4+1] = v.y; tw[i*4+2] = v.z; tw[i*4+3] = v.w;
    }
    float tb = timeb[d];
    __shared__ float feat[64];
    for (int si = 0; si < 64; si++) {
        int s = s0 + si;
        if (d < 64) {
            float t = tstep[b*SS + s] * (1.0f / 180.0f);
            float v = t * selw[d] + selb[d];
            feat[d] = 1.0f - tanhf(v * v);
        }
        __syncthreads();
        float acc = tb;
#pragma unroll
        for (int k = 0; k < 64; k++) acc += feat[k] * tw[k];
        g_tf[((size_t)b*SS + s) * DD + d] = acc;
        __syncthreads();
    }
}

// ---------------- kernel: ux = x @ U^T + Ub  (SGEMM 8192x2048x512, f32x2) ------
#define TM 128
#define TN 128
#define TK 16
__global__ __launch_bounds__(256, 2) void k_gemm_ux(const float* __restrict__ U,
                                                    const float* __restrict__ Ub) {
    __shared__ float As[2][TK][TM + 4];
    __shared__ float Bs[2][TK][TN + 4];
    int m0 = blockIdx.y * TM;
    int n0 = blockIdx.x * TN;
    int t = threadIdx.x;
    int lrow = t >> 2;          // 0..63
    int lcol = (t & 3) * 4;     // 0,4,8,12

    const float* Aptr = g_x + (size_t)(m0 + lrow) * DD + lcol;
    const float* Bptr = U   + (size_t)(n0 + lrow) * DD + lcol;

    float4 ra[2], rb[2];
    ra[0] = *(const float4*)(Aptr);
    ra[1] = *(const float4*)(Aptr + 64*DD);
    rb[0] = *(const float4*)(Bptr);
    rb[1] = *(const float4*)(Bptr + 64*DD);

    int warp = t >> 5;
    int wm   = warp >> 1;
    int wn   = warp & 1;
    int lane = t & 31;
    int lm   = lane >> 3;
    int ln   = lane & 7;
    int ma   = wm*32 + lm*4;
    int nb   = wn*64 + ln*4;

    unsigned long long acc[4][8];
#pragma unroll
    for (int mp = 0; mp < 4; mp++)
#pragma unroll
        for (int nn = 0; nn < 8; nn++) acc[mp][nn] = 0ull;

#pragma unroll
    for (int i = 0; i < 2; i++) {
        int r = lrow + i*64;
        As[0][lcol+0][r] = ra[i].x; As[0][lcol+1][r] = ra[i].y;
        As[0][lcol+2][r] = ra[i].z; As[0][lcol+3][r] = ra[i].w;
        Bs[0][lcol+0][r] = rb[i].x; Bs[0][lcol+1][r] = rb[i].y;
        Bs[0][lcol+2][r] = rb[i].z; Bs[0][lcol+3][r] = rb[i].w;
    }
    __syncthreads();

    const int NT = DD / TK;  // 32
    for (int kt = 0; kt < NT; kt++) {
        if (kt < NT - 1) {
            const float* ap = Aptr + (kt+1)*TK;
            const float* bp = Bptr + (kt+1)*TK;
            ra[0] = *(const float4*)(ap);
            ra[1] = *(const float4*)(ap + 64*DD);
            rb[0] = *(const float4*)(bp);
            rb[1] = *(const float4*)(bp + 64*DD);
        }
        int buf = kt & 1;
#pragma unroll
        for (int k = 0; k < TK; k++) {
            F4U a0, a1, b0, b1;
            a0.f = *(const float4*)&As[buf][k][ma];
            a1.f = *(const float4*)&As[buf][k][ma+16];
            b0.f = *(const float4*)&Bs[buf][k][nb];
            b1.f = *(const float4*)&Bs[buf][k][nb+32];
            unsigned long long ap2[4] = { a0.u[0], a0.u[1], a1.u[0], a1.u[1] };
            float bv[8] = {b0.f.x,b0.f.y,b0.f.z,b0.f.w,b1.f.x,b1.f.y,b1.f.z,b1.f.w};
            unsigned long long bb2[8];
#pragma unroll
            for (int nn = 0; nn < 8; nn++) bb2[nn] = pack2(bv[nn], bv[nn]);
#pragma unroll
            for (int mp = 0; mp < 4; mp++)
#pragma unroll
                for (int nn = 0; nn < 8; nn++)
                    acc[mp][nn] = ffma2(ap2[mp], bb2[nn], acc[mp][nn]);
        }
        if (kt < NT - 1) {
            __syncthreads();
            int nbuf = buf ^ 1;
#pragma unroll
            for (int i = 0; i < 2; i++) {
                int r = lrow + i*64;
                As[nbuf][lcol+0][r] = ra[i].x; As[nbuf][lcol+1][r] = ra[i].y;
                As[nbuf][lcol+2][r] = ra[i].z; As[nbuf][lcol+3][r] = ra[i].w;
                Bs[nbuf][lcol+0][r] = rb[i].x; Bs[nbuf][lcol+1][r] = rb[i].y;
                Bs[nbuf][lcol+2][r] = rb[i].z; Bs[nbuf][lcol+3][r] = rb[i].w;
            }
            __syncthreads();
        }
    }

    float ub[8];
#pragma unroll
    for (int nn = 0; nn < 8; nn++)
        ub[nn] = Ub[n0 + nb + (nn>>2)*32 + (nn&3)];
#pragma unroll
    for (int mp = 0; mp < 4; mp++) {
#pragma unroll
        for (int e = 0; e < 2; e++) {
            int m = m0 + ma + (mp>>1)*16 + (mp&1)*2 + e;
            float* Crow = g_ux + (size_t)m * G4D + n0;
#pragma unroll
            for (int nc = 0; nc < 2; nc++) {
                float4 v;
                float2 p0 = unpack2(acc[mp][nc*4+0]);
                float2 p1 = unpack2(acc[mp][nc*4+1]);
                float2 p2 = unpack2(acc[mp][nc*4+2]);
                float2 p3 = unpack2(acc[mp][nc*4+3]);
                v.x = (e ? p0.y : p0.x) + ub[nc*4+0];
                v.y = (e ? p1.y : p1.x) + ub[nc*4+1];
                v.z = (e ? p2.y : p2.x) + ub[nc*4+2];
                v.w = (e ? p3.y : p3.x) + ub[nc*4+3];
                *(float4*)(Crow + nb + nc*32) = v;
            }
        }
    }
}

// ---------------- persistent recurrent kernel (all 128 steps) -------------------
// 128 CTAs = 64 jg x 2 bg. CTA = 8 j x 32 b -> 40 output rows (5 gates x 8 j).
// 512 threads, 16 warps = 16 k-slices of 32.
// h/c TRANSPOSED: global [j][b], smem k-major HS[k][32b] (128B rows, aligned,
// conflict-free). FFMA2 pairs span TWO BATCHES -> h/c pairs come straight from
// LDS.128, NO packing MOVs (R13 spent 16 MOV/2k packing h/c). Weights row-major
// WS[40][516]; LDS.64 gives (w_k0,w_k1), 10 pack MOVs/2k. Inner 2k: 8 LDS.128 +
// 5 LDS.64 + 10 MOV + 40 FFMA2 = 63 issue slots (vs 74). acc = 40 regs, no spill.
#define NCTA 128
#define JPC 8
#define BPC 32
#define WPAD2 516                  // WS row stride (floats)
#define HPT 32                     // HS/CS row stride (floats) = 128B, aligned
#define RSU 21                     // reduce stride per thread (ull)
#define RNN_SMEM ((40*WPAD2 + 2*DD*HPT) * 4)   // 213632 B

__global__ __launch_bounds__(512) void k_rnn(
        const float* __restrict__ Wall, const float* __restrict__ Wallb,
        const float* __restrict__ Wd,   const float* __restrict__ Wdb) {
    extern __shared__ float sm[];
    float* WS = sm;                       // 40 rows x 516 (row-major)
    float* HS = WS + 40*WPAD2;            // 512 k x 32 b
    float* CS = HS + DD*HPT;              // 512 k x 32 b
    unsigned long long* red = (unsigned long long*)HS;  // aliases HS(+CS head)

    unsigned HSu = (unsigned)__cvta_generic_to_shared(HS);
    unsigned CSu = (unsigned)__cvta_generic_to_shared(CS);

    int t    = threadIdx.x;
    int lane = t & 31;
    int kq   = t >> 5;          // warp id = k-slice 0..15 (32 k each)
    int jj   = lane & 7;        // j-index within CTA (all 5 gates)
    int bq   = lane >> 3;       // batch-quad group 0..3 (8 b = 4 pairs each)
    int jg = blockIdx.x & 63;
    int bg = blockIdx.x >> 6;
    int j0 = jg * JPC;
    int b0 = bg * BPC;

    // ---- weights into smem once: row-major WS[r][k], 512 threads = k columns --
#pragma unroll
    for (int i = 0; i < 40; i++) {
        int g = i >> 3, jj2 = i & 7;
        const float* src = (i < 32)
            ? Wall + (size_t)(g*DD + j0 + jj2) * DD + t
            : Wd   + (size_t)(j0 + (i - 32)) * DD + t;
        WS[i*WPAD2 + t] = *src;
    }
    __syncthreads();

    // epilogue mapping: thread t (<256) -> (b_e, jj_e)
    int b_e  = (t & 255) >> 3;  // 0..31
    int jj_e = t & 7;
    int gb_e = b0 + b_e;
    int j_e  = j0 + jj_e;

    float wdb  = __ldg(Wdb + j_e);
    float wab0 = __ldg(Wallb + 0*DD + j_e);
    float wab1 = __ldg(Wallb + 1*DD + j_e);
    float wab2 = __ldg(Wallb + 2*DD + j_e);
    float wab3 = __ldg(Wallb + 3*DD + j_e);

    // prefetch step-0 tf/ux (lower 256 only)
    float tfv = 0.f, ux0 = 0.f, ux1 = 0.f, ux2 = 0.f, ux3 = 0.f;
    if (t < 256) {
        tfv = __ldg(g_tf + ((size_t)gb_e * SS + 0) * DD + j_e);
        const float* uxr = g_ux + ((size_t)gb_e * SS + 0) * G4D;
        ux0 = __ldg(uxr + 0*DD + j_e);
        ux1 = __ldg(uxr + 1*DD + j_e);
        ux2 = __ldg(uxr + 2*DD + j_e);
        ux3 = __ldg(uxr + 3*DD + j_e);
    }

    for (int s = 0; s < SS; s++) {
        const float* h_in = g_hT[s & 1];
        const float* c_in = g_cT[s & 1];
        float* h_out = g_hT[(s + 1) & 1];
        float* c_out = g_cT[(s + 1) & 1];
        size_t bsoff = ((size_t)gb_e * SS + s);

        // ---- per-warp cp.async: own 32-k slice of h/c, 2 halves of 16 rows ----
        // global row j' (=k): g_hT[k*64 + b0 .. +31] -> HS[k*32 .. +31]
#pragma unroll
        for (int hh = 0; hh < 2; hh++) {
#pragma unroll
            for (int i = 0; i < 4; i++) {
                int lin = hh*128 + i*32 + lane;   // 0..255
                int row = lin >> 3;               // k within slice 0..31
                int c4  = lin & 7;                // 16B chunk (4 floats)
                int kg  = kq*32 + row;
                unsigned so = (unsigned)((kg*HPT + c4*4) * 4);
                cpasync16(HSu + so, h_in + (size_t)kg*BB + b0 + c4*4);
                cpasync16(CSu + so, c_in + (size_t)kg*BB + b0 + c4*4);
            }
            cpasync_commit();
        }

        unsigned long long acc[5][4];
#pragma unroll
        for (int g = 0; g < 5; g++)
#pragma unroll
            for (int q = 0; q < 4; q++) acc[g][q] = 0ull;

        // ---- compute over own 32-wide k-slice ----
#pragma unroll
        for (int hh = 0; hh < 2; hh++) {
            if (hh == 0) cpasync_wait<1>(); else cpasync_wait<0>();
            __syncwarp();
            int kbase = kq*32 + hh*16;
#pragma unroll
            for (int km2 = 0; km2 < 8; km2++) {
                int k0 = kbase + km2*2;
                unsigned long long wraw[5];
#pragma unroll
                for (int g = 0; g < 5; g++)
                    wraw[g] = *(const unsigned long long*)(WS + (g*8 + jj)*WPAD2 + k0);
#pragma unroll
                for (int e2 = 0; e2 < 2; e2++) {
                    int k = k0 + e2;
                    F4U hA, hB, cA, cB;
                    hA.f = *(const float4*)(HS + k*HPT + bq*8);
                    hB.f = *(const float4*)(HS + k*HPT + bq*8 + 4);
                    cA.f = *(const float4*)(CS + k*HPT + bq*8);
                    cB.f = *(const float4*)(CS + k*HPT + bq*8 + 4);
                    unsigned long long hp[4] = {hA.u[0], hA.u[1], hB.u[0], hB.u[1]};
                    unsigned long long cp2[4] = {cA.u[0], cA.u[1], cB.u[0], cB.u[1]};
#pragma unroll
                    for (int g = 0; g < 5; g++) {
                        float2 wu = unpack2(wraw[g]);
                        float wv = e2 ? wu.y : wu.x;
                        unsigned long long wp = pack2(wv, wv);
#pragma unroll
                        for (int q = 0; q < 4; q++)
                            acc[g][q] = ffma2((g < 4) ? hp[q] : cp2[q], wp, acc[g][q]);
                    }
                }
            }
        }

        __syncthreads();                 // all warps' compute done; CS fully valid
        float cprev = (t < 256) ? CS[j_e*HPT + b_e] : 0.0f;
        __syncthreads();                 // cprev reads done before red overwrites

        // ---- store partials: acc[g][q] = (out_{b=bq*8+2q}, out_{b=+1}) ----
#pragma unroll
        for (int g = 0; g < 5; g++)
#pragma unroll
            for (int q = 0; q < 4; q++)
                red[t*RSU + g*4 + q] = acc[g][q];
        __syncthreads();

        // ---- gather + pointwise (lower 256 threads own one (b,j) each) ----
        if (t < 256) {
            const float* rf = (const float*)red;
            int bq_s = b_e >> 3;
            int q_s  = (b_e & 7) >> 1;
            int e_s  = b_e & 1;
            float gate[5];
#pragma unroll
            for (int g = 0; g < 5; g++) {
                float sv = 0.f;
#pragma unroll
                for (int kk = 0; kk < 16; kk++) {
                    int tsrc = kk*32 + bq_s*8 + jj_e;
                    sv += rf[(tsrc*RSU + g*4 + q_s)*2 + e_s];
                }
                gate[g] = sv;
            }

            float cs1 = tanhf(gate[4] + wdb);
            float fg = sigmoidf_(gate[0] + wab0 + ux0);
            float ig = sigmoidf_(gate[1] + wab1 + ux1);
            float og = sigmoidf_(gate[2] + wab2 + ux2);
            float ct = sigmoidf_(gate[3] + wab3 + ux3);

            float cadj = cprev + cs1 * (tfv - 1.0f);
            float cn   = fg * cadj + ig * ct;
            float hn   = og * tanhf(cn);
            c_out[(size_t)j_e*BB + gb_e] = cn;
            h_out[(size_t)j_e*BB + gb_e] = hn;
            g_hs[bsoff * DD + j_e] = hn;
        }

        if (s < SS - 1) {
            // prefetch next step's tf/ux (hidden under barrier)
            if (t < 256) {
                size_t bsoff1 = bsoff + 1;
                tfv = __ldg(g_tf + bsoff1 * DD + j_e);
                const float* uxr1 = g_ux + bsoff1 * G4D;
                ux0 = __ldg(uxr1 + 0*DD + j_e);
                ux1 = __ldg(uxr1 + 1*DD + j_e);
                ux2 = __ldg(uxr1 + 2*DD + j_e);
                ux3 = __ldg(uxr1 + 3*DD + j_e);
            }

            // ---- half-grid barrier for group bg (64 CTAs), no atomics ----
            __syncthreads();
            if (t == 0) {
                __threadfence();
                *(volatile unsigned*)&g_flags[blockIdx.x] = (unsigned)(s + 1);
            }
            if (jg == 0) {
                if (t < 64) {
                    const volatile unsigned* f = (const volatile unsigned*)&g_flags[bg*64 + t];
                    while (*f < (unsigned)(s + 1)) { }
                    __threadfence();
                }
                __syncthreads();
                if (t == 0) {
                    *(volatile unsigned*)&g_release[bg][0] = (unsigned)(s + 1);
                }
            } else {
                if (t == 0) {
                    const volatile unsigned* r = (const volatile unsigned*)&g_release[bg][0];
                    while (*r < (unsigned)(s + 1)) { }
                    __threadfence();
                }
                __syncthreads();
            }
        }
    }
}

// ---------------- kernel: max-pool over S + output head ------------------------
__global__ __launch_bounds__(512) void k_pool(const float* __restrict__ ow,
                                              const float* __restrict__ ob,
                                              float* __restrict__ out) {
    int b = blockIdx.x;
    int d = threadIdx.x;
    const float* p = g_hs + (size_t)b * SS * DD + d;
    float m = -3.0e38f;
#pragma unroll 8
    for (int s = 0; s < SS; s++) m = fmaxf(m, p[(size_t)s * DD]);
    float s0 = m * ow[d];
    float s1 = m * ow[DD + d];
    __shared__ float r0[512], r1[512];
    r0[d] = s0; r1[d] = s1;
    __syncthreads();
    for (int off = 256; off > 0; off >>= 1) {
        if (d < off) { r0[d] += r0[d + off]; r1[d] += r1[d + off]; }
        __syncthreads();
    }
    if (d == 0) {
        out[b*2 + 0] = r0[0] + ob[0];
        out[b*2 + 1] = r1[0] + ob[1];
    }
}

// ---------------- launch --------------------------------------------------------
extern "C" void kernel_launch(void* const* d_in, const int* in_sizes, int n_in,
                              void* d_out, int out_size) {
    const float* emb   = (const float*)d_in[0];
    const float* Wall  = (const float*)d_in[1];
    const float* Wallb = (const float*)d_in[2];
    const float* U     = (const float*)d_in[3];
    const float* Ub    = (const float*)d_in[4];
    const float* Wd    = (const float*)d_in[5];
    const float* Wdb   = (const float*)d_in[6];
    const float* selw  = (const float*)d_in[7];
    const float* selb  = (const float*)d_in[8];
    const float* timew = (const float*)d_in[9];
    const float* timeb = (const float*)d_in[10];
    const float* outw  = (const float*)d_in[11];
    const float* outb  = (const float*)d_in[12];
    const float* tstep = (const float*)d_in[13];
    const int*   seqs  = (const int*)d_in[14];
    float* out = (float*)d_out;

    static int configured = 0;
    if (!configured) {
        cudaFuncSetAttribute(k_rnn, cudaFuncAttributeMaxDynamicSharedMemorySize, RNN_SMEM);
        configured = 1;
    }

    k_zero<<<128, 256>>>();
    k_gather<<<BS, 128>>>(emb, seqs);
    k_tf<<<128, 512>>>(tstep, selw, selb, timew, timeb);
    k_gemm_ux<<<dim3(G4D/TN, BS/TM), 256>>>(U, Ub);
    k_rnn<<<NCTA, 512, RNN_SMEM>>>(Wall, Wallb, Wd, Wdb);
    k_pool<<<BB, 512>>>(outw, outb, out);
}

// round 15
// speedup vs baseline: 1.6698x; 1.0068x over previous
#include <cuda_runtime.h>
#include <cuda_bf16.h>
#include <math.h>

// Problem constants
#define BB 64
#define SS 128
#define CC 32
#define DD 512
#define VV 20000
#define BS (BB*SS)          // 8192
#define G4D (4*DD)          // 2048

// ---------------- device scratch (allocation-free rule: __device__ globals) ----
__device__ float g_x[BS*DD];           // 16 MB  visit embeddings summed
__device__ float g_tf[BS*DD];          // 16 MB  time features
__device__ float g_ux[(size_t)BS*G4D]; // 64 MB  input projection
__device__ float g_hT[2][DD*BB];       // ping-pong hidden, TRANSPOSED [j][b]
__device__ float g_cT[2][DD*BB];       // ping-pong cell,   TRANSPOSED [j][b]
__device__ float g_hs[(size_t)BB*SS*DD]; // 16 MB all hidden states [b][s][d]
__device__ unsigned g_flags[128];      // per-CTA step counters
__device__ unsigned g_release[2][32];  // per-group release words (padded)

// ---------------- f32x2 packed helpers (Blackwell) ----------------------------
__device__ __forceinline__ unsigned long long ffma2(unsigned long long a,
                                                    unsigned long long b,
                                                    unsigned long long c) {
    unsigned long long d;
    asm("fma.rn.f32x2 %0, %1, %2, %3;" : "=l"(d) : "l"(a), "l"(b), "l"(c));
    return d;
}
__device__ __forceinline__ unsigned long long pack2(float lo, float hi) {
    unsigned long long r;
    asm("mov.b64 %0, {%1, %2};" : "=l"(r) : "f"(lo), "f"(hi));
    return r;
}
__device__ __forceinline__ float2 unpack2(unsigned long long v) {
    float2 r;
    asm("mov.b64 {%0, %1}, %2;" : "=f"(r.x), "=f"(r.y) : "l"(v));
    return r;
}
union F4U { float4 f; unsigned long long u[2]; };

__device__ __forceinline__ float sigmoidf_(float x) { return 1.0f / (1.0f + expf(-x)); }

__device__ __forceinline__ void cpasync16(unsigned saddr, const float* g) {
    asm volatile("cp.async.cg.shared.global [%0], [%1], 16;" :: "r"(saddr), "l"(g));
}
__device__ __forceinline__ void cpasync_commit() {
    asm volatile("cp.async.commit_group;");
}
template<int N> __device__ __forceinline__ void cpasync_wait() {
    asm volatile("cp.async.wait_group %0;" :: "n"(N));
}
__device__ __forceinline__ void stcg(float* p, float v) {
    asm volatile("st.global.cg.f32 [%0], %1;" :: "l"(p), "f"(v));
}

// ---------------- kernel: zero h0/c0 + reset barrier state ---------------------
__global__ void k_zero() {
    int i = blockIdx.x * blockDim.x + threadIdx.x;
    if (i < DD*BB) { g_hT[0][i] = 0.0f; g_cT[0][i] = 0.0f; }
    if (i < 128) g_flags[i] = 0u;
    if (i < 64) ((unsigned*)g_release)[i] = 0u;
}

// ---------------- kernel: gather + sum embeddings ------------------------------
__global__ __launch_bounds__(128) void k_gather(const float* __restrict__ emb,
                                                const int* __restrict__ seqs) {
    int bs = blockIdx.x;
    __shared__ int sidx[CC];
    if (threadIdx.x < CC) sidx[threadIdx.x] = seqs[bs*CC + threadIdx.x];
    __syncthreads();
    int d4 = threadIdx.x;  // 0..127
    float4 acc = make_float4(0.f, 0.f, 0.f, 0.f);
#pragma unroll 8
    for (int c = 0; c < CC; c++) {
        const float4* row = (const float4*)(emb + (size_t)sidx[c] * DD);
        float4 v = __ldg(row + d4);
        acc.x += v.x; acc.y += v.y; acc.z += v.z; acc.w += v.w;
    }
    ((float4*)(g_x + (size_t)bs * DD))[d4] = acc;
}

// ---------------- kernel: time feature ----------------------------------------
__global__ __launch_bounds__(512) void k_tf(const float* __restrict__ tstep,
                                            const float* __restrict__ selw,
                                            const float* __restrict__ selb,
                                            const float* __restrict__ timew,
                                            const float* __restrict__ timeb) {
    int b  = blockIdx.x >> 1;
    int s0 = (blockIdx.x & 1) * 64;
    int d  = threadIdx.x;
    float tw[64];
    const float4* twp = (const float4*)(timew + (size_t)d * 64);
#pragma unroll
    for (int i = 0; i < 16; i++) {
        float4 v = __ldg(twp + i);
        tw[i*4+0] = v.x; tw[i*4+1] = v.y; tw[i*4+2] = v.z; tw[i*4+3] = v.w;
    }
    float tb = timeb[d];
    __shared__ float feat[64];
    for (int si = 0; si < 64; si++) {
        int s = s0 + si;
        if (d < 64) {
            float t = tstep[b*SS + s] * (1.0f / 180.0f);
            float v = t * selw[d] + selb[d];
            feat[d] = 1.0f - tanhf(v * v);
        }
        __syncthreads();
        float acc = tb;
#pragma unroll
        for (int k = 0; k < 64; k++) acc += feat[k] * tw[k];
        g_tf[((size_t)b*SS + s) * DD + d] = acc;
        __syncthreads();
    }
}

// ---------------- kernel: ux = x @ U^T + Ub  (SGEMM 8192x2048x512, f32x2) ------
#define TM 128
#define TN 128
#define TK 16
__global__ __launch_bounds__(256, 2) void k_gemm_ux(const float* __restrict__ U,
                                                    const float* __restrict__ Ub) {
    __shared__ float As[2][TK][TM + 4];
    __shared__ float Bs[2][TK][TN + 4];
    int m0 = blockIdx.y * TM;
    int n0 = blockIdx.x * TN;
    int t = threadIdx.x;
    int lrow = t >> 2;          // 0..63
    int lcol = (t & 3) * 4;     // 0,4,8,12

    const float* Aptr = g_x + (size_t)(m0 + lrow) * DD + lcol;
    const float* Bptr = U   + (size_t)(n0 + lrow) * DD + lcol;

    float4 ra[2], rb[2];
    ra[0] = *(const float4*)(Aptr);
    ra[1] = *(const float4*)(Aptr + 64*DD);
    rb[0] = *(const float4*)(Bptr);
    rb[1] = *(const float4*)(Bptr + 64*DD);

    int warp = t >> 5;
    int wm   = warp >> 1;
    int wn   = warp & 1;
    int lane = t & 31;
    int lm   = lane >> 3;
    int ln   = lane & 7;
    int ma   = wm*32 + lm*4;
    int nb   = wn*64 + ln*4;

    unsigned long long acc[4][8];
#pragma unroll
    for (int mp = 0; mp < 4; mp++)
#pragma unroll
        for (int nn = 0; nn < 8; nn++) acc[mp][nn] = 0ull;

#pragma unroll
    for (int i = 0; i < 2; i++) {
        int r = lrow + i*64;
        As[0][lcol+0][r] = ra[i].x; As[0][lcol+1][r] = ra[i].y;
        As[0][lcol+2][r] = ra[i].z; As[0][lcol+3][r] = ra[i].w;
        Bs[0][lcol+0][r] = rb[i].x; Bs[0][lcol+1][r] = rb[i].y;
        Bs[0][lcol+2][r] = rb[i].z; Bs[0][lcol+3][r] = rb[i].w;
    }
    __syncthreads();

    const int NT = DD / TK;  // 32
    for (int kt = 0; kt < NT; kt++) {
        if (kt < NT - 1) {
            const float* ap = Aptr + (kt+1)*TK;
            const float* bp = Bptr + (kt+1)*TK;
            ra[0] = *(const float4*)(ap);
            ra[1] = *(const float4*)(ap + 64*DD);
            rb[0] = *(const float4*)(bp);
            rb[1] = *(const float4*)(bp + 64*DD);
        }
        int buf = kt & 1;
#pragma unroll
        for (int k = 0; k < TK; k++) {
            F4U a0, a1, b0, b1;
            a0.f = *(const float4*)&As[buf][k][ma];
            a1.f = *(const float4*)&As[buf][k][ma+16];
            b0.f = *(const float4*)&Bs[buf][k][nb];
            b1.f = *(const float4*)&Bs[buf][k][nb+32];
            unsigned long long ap2[4] = { a0.u[0], a0.u[1], a1.u[0], a1.u[1] };
            float bv[8] = {b0.f.x,b0.f.y,b0.f.z,b0.f.w,b1.f.x,b1.f.y,b1.f.z,b1.f.w};
            unsigned long long bb2[8];
#pragma unroll
            for (int nn = 0; nn < 8; nn++) bb2[nn] = pack2(bv[nn], bv[nn]);
#pragma unroll
            for (int mp = 0; mp < 4; mp++)
#pragma unroll
                for (int nn = 0; nn < 8; nn++)
                    acc[mp][nn] = ffma2(ap2[mp], bb2[nn], acc[mp][nn]);
        }
        if (kt < NT - 1) {
            __syncthreads();
            int nbuf = buf ^ 1;
#pragma unroll
            for (int i = 0; i < 2; i++) {
                int r = lrow + i*64;
                As[nbuf][lcol+0][r] = ra[i].x; As[nbuf][lcol+1][r] = ra[i].y;
                As[nbuf][lcol+2][r] = ra[i].z; As[nbuf][lcol+3][r] = ra[i].w;
                Bs[nbuf][lcol+0][r] = rb[i].x; Bs[nbuf][lcol+1][r] = rb[i].y;
                Bs[nbuf][lcol+2][r] = rb[i].z; Bs[nbuf][lcol+3][r] = rb[i].w;
            }
            __syncthreads();
        }
    }

    float ub[8];
#pragma unroll
    for (int nn = 0; nn < 8; nn++)
        ub[nn] = Ub[n0 + nb + (nn>>2)*32 + (nn&3)];
#pragma unroll
    for (int mp = 0; mp < 4; mp++) {
#pragma unroll
        for (int e = 0; e < 2; e++) {
            int m = m0 + ma + (mp>>1)*16 + (mp&1)*2 + e;
            float* Crow = g_ux + (size_t)m * G4D + n0;
#pragma unroll
            for (int nc = 0; nc < 2; nc++) {
                float4 v;
                float2 p0 = unpack2(acc[mp][nc*4+0]);
                float2 p1 = unpack2(acc[mp][nc*4+1]);
                float2 p2 = unpack2(acc[mp][nc*4+2]);
                float2 p3 = unpack2(acc[mp][nc*4+3]);
                v.x = (e ? p0.y : p0.x) + ub[nc*4+0];
                v.y = (e ? p1.y : p1.x) + ub[nc*4+1];
                v.z = (e ? p2.y : p2.x) + ub[nc*4+2];
                v.w = (e ? p3.y : p3.x) + ub[nc*4+3];
                *(float4*)(Crow + nb + nc*32) = v;
            }
        }
    }
}

// ---------------- persistent recurrent kernel (all 128 steps) -------------------
// 128 CTAs = 64 jg x 2 bg. CTA = 8 j x 32 b. 512 threads, 16 warps = 16 k-slices
// of 32. h/c transposed [j][b]; smem k-major HS[k][32b]. FFMA2 pairs span two
// batches (no h/c packing MOVs).
// NEW R15: h-pass/c-pass split + fine-grained cp.async chunks. h loads in 4
// chunks of 8 k-rows (waits <5..2>), c in 2 of 16 (<1>,<0>). All h-gate compute
// (32 of 40 FFMA2 per 2k) starts after ~12% of the post-barrier L2 burst instead
// of ~50%, and the entire c transfer hides behind h compute.
#define NCTA 128
#define JPC 8
#define BPC 32
#define WPAD2 516                  // WS row stride (floats)
#define HPT 32                     // HS/CS row stride (floats) = 128B, aligned
#define RSU 21                     // reduce stride per thread (ull)
#define RNN_SMEM ((40*WPAD2 + 2*DD*HPT) * 4)   // 213632 B

__global__ __launch_bounds__(512) void k_rnn(
        const float* __restrict__ Wall, const float* __restrict__ Wallb,
        const float* __restrict__ Wd,   const float* __restrict__ Wdb) {
    extern __shared__ float sm[];
    float* WS = sm;                       // 40 rows x 516 (row-major)
    float* HS = WS + 40*WPAD2;            // 512 k x 32 b
    float* CS = HS + DD*HPT;              // 512 k x 32 b
    unsigned long long* red = (unsigned long long*)HS;  // aliases HS(+CS head)

    unsigned HSu = (unsigned)__cvta_generic_to_shared(HS);
    unsigned CSu = (unsigned)__cvta_generic_to_shared(CS);

    int t    = threadIdx.x;
    int lane = t & 31;
    int kq   = t >> 5;          // warp id = k-slice 0..15 (32 k each)
    int jj   = lane & 7;        // j-index within CTA (all 5 gates)
    int bq   = lane >> 3;       // batch-quad group 0..3 (8 b = 4 pairs each)
    int jg = blockIdx.x & 63;
    int bg = blockIdx.x >> 6;
    int j0 = jg * JPC;
    int b0 = bg * BPC;

    // ---- weights into smem once: row-major WS[r][k], 512 threads = k columns --
#pragma unroll
    for (int i = 0; i < 40; i++) {
        int g = i >> 3, jj2 = i & 7;
        const float* src = (i < 32)
            ? Wall + (size_t)(g*DD + j0 + jj2) * DD + t
            : Wd   + (size_t)(j0 + (i - 32)) * DD + t;
        WS[i*WPAD2 + t] = *src;
    }
    __syncthreads();

    // epilogue mapping: thread t (<256) -> (b_e, jj_e)
    int b_e  = (t & 255) >> 3;  // 0..31
    int jj_e = t & 7;
    int gb_e = b0 + b_e;
    int j_e  = j0 + jj_e;

    float wdb  = __ldg(Wdb + j_e);
    float wab0 = __ldg(Wallb + 0*DD + j_e);
    float wab1 = __ldg(Wallb + 1*DD + j_e);
    float wab2 = __ldg(Wallb + 2*DD + j_e);
    float wab3 = __ldg(Wallb + 3*DD + j_e);

    // prefetch step-0 tf/ux (lower 256 only)
    float tfv = 0.f, ux0 = 0.f, ux1 = 0.f, ux2 = 0.f, ux3 = 0.f;
    if (t < 256) {
        tfv = __ldg(g_tf + ((size_t)gb_e * SS + 0) * DD + j_e);
        const float* uxr = g_ux + ((size_t)gb_e * SS + 0) * G4D;
        ux0 = __ldg(uxr + 0*DD + j_e);
        ux1 = __ldg(uxr + 1*DD + j_e);
        ux2 = __ldg(uxr + 2*DD + j_e);
        ux3 = __ldg(uxr + 3*DD + j_e);
    }

    for (int s = 0; s < SS; s++) {
        const float* h_in = g_hT[s & 1];
        const float* c_in = g_cT[s & 1];
        float* h_out = g_hT[(s + 1) & 1];
        float* c_out = g_cT[(s + 1) & 1];
        size_t bsoff = ((size_t)gb_e * SS + s);

        // ---- issue h chunks FIRST (4 x 8 k-rows), then c (2 x 16 k-rows) ----
#pragma unroll
        for (int ch = 0; ch < 4; ch++) {
#pragma unroll
            for (int i = 0; i < 2; i++) {
                int lin = i*32 + lane;            // 0..63
                int row = lin >> 3, c4 = lin & 7; // row 0..7
                int kg = kq*32 + ch*8 + row;
                unsigned so = (unsigned)((kg*HPT + c4*4) * 4);
                cpasync16(HSu + so, h_in + (size_t)kg*BB + b0 + c4*4);
            }
            cpasync_commit();
        }
#pragma unroll
        for (int cc = 0; cc < 2; cc++) {
#pragma unroll
            for (int i = 0; i < 4; i++) {
                int lin = i*32 + lane;            // 0..127
                int row = lin >> 3, c4 = lin & 7; // row 0..15
                int kg = kq*32 + cc*16 + row;
                unsigned so = (unsigned)((kg*HPT + c4*4) * 4);
                cpasync16(CSu + so, c_in + (size_t)kg*BB + b0 + c4*4);
            }
            cpasync_commit();
        }

        unsigned long long acc[5][4];
#pragma unroll
        for (int g = 0; g < 5; g++)
#pragma unroll
            for (int q = 0; q < 4; q++) acc[g][q] = 0ull;

        // ---- h pass: gates 0..3 over own 32-k slice, chunked 8 rows ----
        auto h_chunk = [&](int ch) {
            int kbase = kq*32 + ch*8;
#pragma unroll
            for (int km2 = 0; km2 < 4; km2++) {
                int k0 = kbase + km2*2;
                unsigned long long wraw[4];
#pragma unroll
                for (int g = 0; g < 4; g++)
                    wraw[g] = *(const unsigned long long*)(WS + (g*8 + jj)*WPAD2 + k0);
#pragma unroll
                for (int e2 = 0; e2 < 2; e2++) {
                    int k = k0 + e2;
                    F4U hA, hB;
                    hA.f = *(const float4*)(HS + k*HPT + bq*8);
                    hB.f = *(const float4*)(HS + k*HPT + bq*8 + 4);
                    unsigned long long hp[4] = {hA.u[0], hA.u[1], hB.u[0], hB.u[1]};
#pragma unroll
                    for (int g = 0; g < 4; g++) {
                        float2 wu = unpack2(wraw[g]);
                        float wv = e2 ? wu.y : wu.x;
                        unsigned long long wp = pack2(wv, wv);
#pragma unroll
                        for (int q = 0; q < 4; q++)
                            acc[g][q] = ffma2(hp[q], wp, acc[g][q]);
                    }
                }
            }
        };
        cpasync_wait<5>(); __syncwarp(); h_chunk(0);
        cpasync_wait<4>(); __syncwarp(); h_chunk(1);
        cpasync_wait<3>(); __syncwarp(); h_chunk(2);
        cpasync_wait<2>(); __syncwarp(); h_chunk(3);

        // ---- c pass: gate 4 (Wd x c), chunked 16 rows ----
        auto c_chunk = [&](int cc) {
            int kbase = kq*32 + cc*16;
#pragma unroll
            for (int km2 = 0; km2 < 8; km2++) {
                int k0 = kbase + km2*2;
                unsigned long long wraw =
                    *(const unsigned long long*)(WS + (32 + jj)*WPAD2 + k0);
#pragma unroll
                for (int e2 = 0; e2 < 2; e2++) {
                    int k = k0 + e2;
                    F4U cA, cB;
                    cA.f = *(const float4*)(CS + k*HPT + bq*8);
                    cB.f = *(const float4*)(CS + k*HPT + bq*8 + 4);
                    unsigned long long cp2[4] = {cA.u[0], cA.u[1], cB.u[0], cB.u[1]};
                    float2 wu = unpack2(wraw);
                    float wv = e2 ? wu.y : wu.x;
                    unsigned long long wp = pack2(wv, wv);
#pragma unroll
                    for (int q = 0; q < 4; q++)
                        acc[4][q] = ffma2(cp2[q], wp, acc[4][q]);
                }
            }
        };
        cpasync_wait<1>(); __syncwarp(); c_chunk(0);
        cpasync_wait<0>(); __syncwarp(); c_chunk(1);

        __syncthreads();                 // all warps' compute done; CS fully valid
        float cprev = (t < 256) ? CS[j_e*HPT + b_e] : 0.0f;
        __syncthreads();                 // cprev reads done before red overwrites

        // ---- store partials: acc[g][q] = (out_{b=bq*8+2q}, out_{b=+1}) ----
#pragma unroll
        for (int g = 0; g < 5; g++)
#pragma unroll
            for (int q = 0; q < 4; q++)
                red[t*RSU + g*4 + q] = acc[g][q];
        __syncthreads();

        // ---- gather + pointwise (lower 256 threads own one (b,j) each) ----
        if (t < 256) {
            const float* rf = (const float*)red;
            int bq_s = b_e >> 3;
            int q_s  = (b_e & 7) >> 1;
            int e_s  = b_e & 1;
            float gate[5];
#pragma unroll
            for (int g = 0; g < 5; g++) {
                float sv = 0.f;
#pragma unroll
                for (int kk = 0; kk < 16; kk++) {
                    int tsrc = kk*32 + bq_s*8 + jj_e;
                    sv += rf[(tsrc*RSU + g*4 + q_s)*2 + e_s];
                }
                gate[g] = sv;
            }

            float cs1 = tanhf(gate[4] + wdb);
            float fg = sigmoidf_(gate[0] + wab0 + ux0);
            float ig = sigmoidf_(gate[1] + wab1 + ux1);
            float og = sigmoidf_(gate[2] + wab2 + ux2);
            float ct = sigmoidf_(gate[3] + wab3 + ux3);

            float cadj = cprev + cs1 * (tfv - 1.0f);
            float cn   = fg * cadj + ig * ct;
            float hn   = og * tanhf(cn);
            stcg(c_out + (size_t)j_e*BB + gb_e, cn);
            stcg(h_out + (size_t)j_e*BB + gb_e, hn);
            stcg(g_hs + bsoff * DD + j_e, hn);
        }

        if (s < SS - 1) {
            // prefetch next step's tf/ux (hidden under barrier)
            if (t < 256) {
                size_t bsoff1 = bsoff + 1;
                tfv = __ldg(g_tf + bsoff1 * DD + j_e);
                const float* uxr1 = g_ux + bsoff1 * G4D;
                ux0 = __ldg(uxr1 + 0*DD + j_e);
                ux1 = __ldg(uxr1 + 1*DD + j_e);
                ux2 = __ldg(uxr1 + 2*DD + j_e);
                ux3 = __ldg(uxr1 + 3*DD + j_e);
            }

            // ---- half-grid barrier for group bg (64 CTAs), no atomics ----
            __syncthreads();
            if (t == 0) {
                __threadfence();
                *(volatile unsigned*)&g_flags[blockIdx.x] = (unsigned)(s + 1);
            }
            if (jg == 0) {
                if (t < 64) {
                    const volatile unsigned* f = (const volatile unsigned*)&g_flags[bg*64 + t];
                    while (*f < (unsigned)(s + 1)) { }
                    __threadfence();
                }
                __syncthreads();
                if (t == 0) {
                    *(volatile unsigned*)&g_release[bg][0] = (unsigned)(s + 1);
                }
            } else {
                if (t == 0) {
                    const volatile unsigned* r = (const volatile unsigned*)&g_release[bg][0];
                    while (*r < (unsigned)(s + 1)) { }
                    __threadfence();
                }
                __syncthreads();
            }
        }
    }
}

// ---------------- kernel: max-pool over S + output head ------------------------
__global__ __launch_bounds__(512) void k_pool(const float* __restrict__ ow,
                                              const float* __restrict__ ob,
                                              float* __restrict__ out) {
    int b = blockIdx.x;
    int d = threadIdx.x;
    const float* p = g_hs + (size_t)b * SS * DD + d;
    float m = -3.0e38f;
#pragma unroll 8
    for (int s = 0; s < SS; s++) m = fmaxf(m, p[(size_t)s * DD]);
    float s0 = m * ow[d];
    float s1 = m * ow[DD + d];
    __shared__ float r0[512], r1[512];
    r0[d] = s0; r1[d] = s1;
    __syncthreads();
    for (int off = 256; off > 0; off >>= 1) {
        if (d < off) { r0[d] += r0[d + off]; r1[d] += r1[d + off]; }
        __syncthreads();
    }
    if (d == 0) {
        out[b*2 + 0] = r0[0] + ob[0];
        out[b*2 + 1] = r1[0] + ob[1];
    }
}

// ---------------- launch --------------------------------------------------------
extern "C" void kernel_launch(void* const* d_in, const int* in_sizes, int n_in,
                              void* d_out, int out_size) {
    const float* emb   = (const float*)d_in[0];
    const float* Wall  = (const float*)d_in[1];
    const float* Wallb = (const float*)d_in[2];
    const float* U     = (const float*)d_in[3];
    const float* Ub    = (const float*)d_in[4];
    const float* Wd    = (const float*)d_in[5];
    const float* Wdb   = (const float*)d_in[6];
    const float* selw  = (const float*)d_in[7];
    const float* selb  = (const float*)d_in[8];
    const float* timew = (const float*)d_in[9];
    const float* timeb = (const float*)d_in[10];
    const float* outw  = (const float*)d_in[11];
    const float* outb  = (const float*)d_in[12];
    const float* tstep = (const float*)d_in[13];
    const int*   seqs  = (const int*)d_in[14];
    float* out = (float*)d_out;

    static int configured = 0;
    if (!configured) {
        cudaFuncSetAttribute(k_rnn, cudaFuncAttributeMaxDynamicSharedMemorySize, RNN_SMEM);
        configured = 1;
    }

    k_zero<<<128, 256>>>();
    k_gather<<<BS, 128>>>(emb, seqs);
    k_tf<<<128, 512>>>(tstep, selw, selb, timew, timeb);
    k_gemm_ux<<<dim3(G4D/TN, BS/TM), 256>>>(U, Ub);
    k_rnn<<<NCTA, 512, RNN_SMEM>>>(Wall, Wallb, Wd, Wdb);
    k_pool<<<BB, 512>>>(outw, outb, out);
}